// round 8
// baseline (speedup 1.0000x reference)
#include <cuda_runtime.h>
#include <math.h>

#define NB 8
#define NA 21504
#define NG 60
#define NC 15
#define BA (NB*NA)
#define NBG (NB*NG)
#define L0N 16384
#define L1N 20480
#define LOG4F 1.3862943611198906f
#define FULLM 0xffffffffu
#define NSEG 336   // 84 tiles * 4 warps

// ---------------- static device scratch ----------------
__device__ float g_bx[BA], g_by[BA];
__device__ float g_a2[BA], g_b2[BA], g_c2[BA], g_d2s[BA], g_ld2[BA];
__device__ float g_obj[BA], g_S[BA];
__device__ float g_lc[NC*BA];                 // [c][b*A+a]
__device__ float g_gcx[NBG], g_gcy[NBG], g_ghw[NBG], g_ghh[NBG];
__device__ float g_ga1[NBG], g_gb1[NBG], g_gc1[NBG], g_gd1s[NBG], g_gld1[NBG];
__device__ int   g_gcls[NBG], g_gvalid[NBG];
__device__ int   g_dynk[NBG];
__device__ float g_thrC[NBG];
__device__ int   g_thrI[NBG];
__device__ float g_pt[NBG*NSEG*10];           // partial top-iou lists (desc)
__device__ float g_pc[NBG*NSEG*10];           // partial bot-cost lists (asc)
__device__ int   g_pi[NBG*NSEG*10];
__device__ float g_acc[5];   // 0: sum(1-iou_m), 1: bce_obj, 2: bce_cls, 3: num_fg, 4: num_gts

// ---------------- deterministic pair iou/cost (shared by k_costred & k_loss) ----------------
// All arithmetic in explicit intrinsics -> bitwise identical across kernels.
__device__ __forceinline__ void pair_cost(
    float ga, float gb, float gc, float gcx, float gcy, float gld1,
    float a2, float b2, float c2, float bx, float by, float lbase,
    float S, float lc, float pb, float pc,
    float& iou, float& cost)
{
    float Af = __fadd_rn(ga, a2);
    float Bf = __fadd_rn(gb, b2);
    float Cf = __fadd_rn(gc, c2);
    float dx = __fsub_rn(gcx, bx);
    float dy = __fsub_rn(gcy, by);
    float cc = __fmul_rn(Cf, Cf);
    float den = __fadd_rn(__fmaf_rn(Af, Bf, -cc), 1e-8f);
    float rden = __fdividef(1.f, den);
    float dx2 = __fmul_rn(dx, dx);
    float dy2 = __fmul_rn(dy, dy);
    float t1 = __fmul_rn(__fmul_rn(0.25f, __fmaf_rn(Af, dy2, __fmul_rn(Bf, dx2))), rden);
    float t2 = __fmul_rn(__fmul_rn(-0.5f, __fmul_rn(Cf, __fmul_rn(dx, dy))), rden);
    float t3 = __fmul_rn(0.5f, __fsub_rn(__logf(den), __fadd_rn(gld1, lbase)));
    float bd = fminf(fmaxf(__fadd_rn(__fadd_rn(t1, t2), t3), 1e-8f), 100.f);
    float q = fminf(fmaxf(__fsub_rn(1.f, __expf(-bd)), 1e-20f), 1.f);
    iou = __fsub_rn(1.f, __fmul_rn(q, __frsqrt_rn(q)));
    float base = __fadd_rn(__fadd_rn(__fadd_rn(S, lc), pb), pc);
    cost = __fmaf_rn(-3.f, __logf(__fadd_rn(iou, 1e-8f)), base);
}

// ---------------- K1b: GT prep + zero accumulators (1 block) ----------------
__global__ void k_gt(const float* __restrict__ labels) {
    int t = threadIdx.x;
    if (t < 5) g_acc[t] = 0.f;
    __syncthreads();
    if (t >= NBG) return;
    const float* L = labels + (size_t)t * 6;
    float l0 = L[0], l1 = L[1], l2 = L[2], l3 = L[3], l4 = L[4], l5 = L[5];
    float sum = l0 + l1 + l2 + l3 + l4 + l5;
    int valid = (sum > 0.f) ? 1 : 0;
    float sn, cs; __sincosf(l5, &sn, &cs);
    float w2 = l3*l3/12.0f, h2 = l4*l4/12.0f;
    float a1 = w2*cs*cs + h2*sn*sn;
    float b1 = w2*sn*sn + h2*cs*cs;
    float c1 = (w2 - h2) * cs * sn;
    float d1 = fmaxf(a1*b1 - c1*c1, 0.f);
    float d1s = d1 * __frsqrt_rn(fmaxf(d1, 1e-30f));
    g_gcx[t] = l1; g_gcy[t] = l2;
    g_ghw[t] = 0.5f * l3; g_ghh[t] = 0.5f * l4;
    g_ga1[t] = a1; g_gb1[t] = b1; g_gc1[t] = c1;
    g_gd1s[t] = d1s;
    g_gld1[t] = __logf(fmaxf(d1s, 1e-35f));
    g_gcls[t] = (int)l0;
    g_gvalid[t] = valid;
    if (valid) atomicAdd(&g_acc[4], 1.f);
}

// ---------------- K1: decode anchors ----------------
__global__ void k_decode(const float* __restrict__ o8,
                         const float* __restrict__ o16,
                         const float* __restrict__ o32) {
    int t = blockIdx.x * blockDim.x + threadIdx.x;
    if (t >= BA) return;
    int b = t / NA;
    int a = t - b * NA;
    const float* src; int hw, i; float st; int gx, gy;
    if (a < L0N)       { src = o8;  hw = 16384; i = a;        st = 8.f;  gx = i & 127; gy = i >> 7; }
    else if (a < L1N)  { src = o16; hw = 4096;  i = a - L0N;  st = 16.f; gx = i & 63;  gy = i >> 6; }
    else               { src = o32; hw = 1024;  i = a - L1N;  st = 32.f; gx = i & 31;  gy = i >> 5; }
    const float* p0 = src + (size_t)b * 21 * hw + i;
    float r0 = p0[0], r1 = p0[hw], r2 = p0[2*hw], r3 = p0[3*hw], r4 = p0[4*hw], r5 = p0[5*hw];
    float bx = (r0 + (float)gx) * st;
    float by = (r1 + (float)gy) * st;
    float bw = __expf(r2) * st;
    float bh = __expf(r3) * st;
    float sn, cs; __sincosf(r4, &sn, &cs);
    float w2 = bw * bw / 12.0f, h2 = bh * bh / 12.0f;
    float a2 = w2*cs*cs + h2*sn*sn;
    float b2 = w2*sn*sn + h2*cs*cs;
    float c2 = (w2 - h2) * cs * sn;
    float d2 = fmaxf(a2*b2 - c2*c2, 0.f);
    float d2s = d2 * __frsqrt_rn(fmaxf(d2, 1e-30f));
    g_bx[t] = bx; g_by[t] = by;
    g_a2[t] = a2; g_b2[t] = b2; g_c2[t] = c2;
    g_d2s[t] = d2s;
    g_ld2[t] = __logf(fmaxf(d2s, 1e-35f));
    g_obj[t] = r5;
    float so = __fdividef(1.f, 1.f + __expf(-r5));
    float S = 0.f;
    #pragma unroll
    for (int c = 0; c < NC; c++) {
        float x = p0[(6 + c) * hw];
        float sc = __fdividef(1.f, 1.f + __expf(-x));
        float q = sc * so;
        float p = q * __frsqrt_rn(fmaxf(q, 1e-30f));
        p = fminf(fmaxf(p, 1e-7f), 1.f - 1e-7f);
        float lg = __logf(1.f - p);
        float lp = __logf(p);
        S -= lg;
        g_lc[c * BA + t] = lg - lp;
    }
    g_S[t] = S;
}

// ---------------- warp-distributed top-10 helpers (lanes 0..9 hold list) ----------------
__device__ __forceinline__ bool pless(float c1, int i1, float c2, int i2) {
    return (c1 < c2) || (c1 == c2 && i1 < i2);
}
__device__ __forceinline__ void wins_top(float& tv, int lane, float c) {
    unsigned bm = __ballot_sync(FULLM, (lane < 10) && (c > tv)) & 0x3FFu;
    if (bm) {
        int p = __ffs(bm) - 1;
        float up = __shfl_up_sync(FULLM, tv, 1);
        if (lane < 10 && lane >= p) tv = (lane == p) ? c : up;
    }
}
__device__ __forceinline__ void wins_bot(float& bcv, int& biv, int lane, float c, int i) {
    unsigned bm = __ballot_sync(FULLM, (lane < 10) && pless(c, i, bcv, biv)) & 0x3FFu;
    if (bm) {
        int p = __ffs(bm) - 1;
        float uc = __shfl_up_sync(FULLM, bcv, 1);
        int   ui = __shfl_up_sync(FULLM, biv, 1);
        if (lane < 10 && lane >= p) { bcv = (lane == p) ? c : uc; biv = (lane == p) ? i : ui; }
    }
}

// ---------------- K2: fused cost + per-(g,warp) partial selection ----------------
// Only cand anchors are computed/inserted. Valid: cand-cost <= 1e5+320 < 1e6-16 <= non-cand
// cost, and every valid GT has >=16 cand anchors (in_ctr geometry), so global bottom-10 is
// within cand. Top-iou: non-cand contribute e=0, which is sum-neutral for dyn_k.
__global__ void k_costred() {
    int b = blockIdx.x / 84;
    int tile = blockIdx.x - b * 84;
    int tid = threadIdx.x;
    int w = tid >> 5, lane = tid & 31;
    int a0 = tile * 256 + 2 * tid;          // even; a0+1 same level/row
    int t0 = b * NA + a0;
    __shared__ float s_cx[NG], s_cy[NG], s_hw[NG], s_hh[NG];
    __shared__ float s_a1[NG], s_b1[NG], s_c1[NG], s_ld1[NG];
    __shared__ int   s_cls[NG], s_val[NG];
    if (tid < NG) {
        int gi = b * NG + tid;
        int v = g_gvalid[gi];
        s_val[tid] = v;
        s_cx[tid] = v ? g_gcx[gi] : 3.0e9f;
        s_cy[tid] = v ? g_gcy[gi] : 3.0e9f;
        s_hw[tid] = g_ghw[gi]; s_hh[tid] = g_ghh[gi];
        s_a1[tid] = g_ga1[gi]; s_b1[tid] = g_gb1[gi];
        s_c1[tid] = g_gc1[gi]; s_ld1[tid] = g_gld1[gi];
        s_cls[tid] = g_gcls[gi];
    }
    __syncthreads();
    float st; int lvlbase, shx, mskx;
    if (a0 < L0N)      { st = 8.f;  lvlbase = 0;    shx = 7; mskx = 127; }
    else if (a0 < L1N) { st = 16.f; lvlbase = L0N;  shx = 6; mskx = 63; }
    else               { st = 32.f; lvlbase = L1N;  shx = 5; mskx = 31; }
    int i0 = a0 - lvlbase;
    float xc0 = ((float)(i0 & mskx) + 0.5f) * st;
    float yc0 = ((float)(i0 >> shx) + 0.5f) * st;
    float xc1 = xc0 + st;
    float rad = 2.5f * st;

    float2 bx01 = *(const float2*)&g_bx[t0];
    float2 by01 = *(const float2*)&g_by[t0];
    float2 A01  = *(const float2*)&g_a2[t0];
    float2 B01  = *(const float2*)&g_b2[t0];
    float2 C01  = *(const float2*)&g_c2[t0];
    float2 S01  = *(const float2*)&g_S[t0];
    float2 ld01 = *(const float2*)&g_ld2[t0];
    float lb0 = ld01.x + LOG4F, lb1 = ld01.y + LOG4F;

    unsigned long long both0 = 0ULL, both1 = 0ULL;
    bool c0 = false, c1 = false;
    #pragma unroll 4
    for (int g = 0; g < NG; g++) {
        float cx = s_cx[g], cy = s_cy[g], hwv = s_hw[g], hh = s_hh[g];
        float dx0 = fabsf(xc0 - cx), dy0 = fabsf(yc0 - cy);
        float dx1 = fabsf(xc1 - cx);
        bool ib0 = (dx0 < hwv) & (dy0 < hh);
        bool ic0 = (dx0 < rad) & (dy0 < rad);
        bool ib1 = (dx1 < hwv) & (dy0 < hh);
        bool ic1 = (dx1 < rad) & (dy0 < rad);
        c0 |= ib0 | ic0; c1 |= ib1 | ic1;
        if (ib0 & ic0) both0 |= (1ULL << g);
        if (ib1 & ic1) both1 |= (1ULL << g);
    }
    float pc0 = c0 ? 0.f : 1e6f;
    float pc1 = c1 ? 0.f : 1e6f;
    unsigned mc0 = __ballot_sync(FULLM, c0);
    unsigned mc1 = __ballot_sync(FULLM, c1);
    int seg = tile * 4 + w;
    int awbase = tile * 256 + (w << 6);     // warp's first anchor

    float iou0 = 0.f, cst0 = 0.f, iou1 = 0.f, cst1 = 0.f;
    for (int g = 0; g < NG; g++) {
        if (!s_val[g]) continue;
        float tv = 0.f, bcv = 3.0e38f; int biv = 0x7fffffff;
        if (c0) {
            float lc = g_lc[s_cls[g] * BA + t0];
            float pb = ((both0 >> g) & 1ULL) ? 0.f : 1e5f;
            pair_cost(s_a1[g], s_b1[g], s_c1[g], s_cx[g], s_cy[g], s_ld1[g],
                      A01.x, B01.x, C01.x, bx01.x, by01.x, lb0, S01.x, lc, pb, pc0,
                      iou0, cst0);
        }
        if (c1) {
            float lc = g_lc[s_cls[g] * BA + t0 + 1];
            float pb = ((both1 >> g) & 1ULL) ? 0.f : 1e5f;
            pair_cost(s_a1[g], s_b1[g], s_c1[g], s_cx[g], s_cy[g], s_ld1[g],
                      A01.y, B01.y, C01.y, bx01.y, by01.y, lb1, S01.y, lc, pb, pc1,
                      iou1, cst1);
        }
        unsigned m = mc0;
        while (m) {
            int src = __ffs(m) - 1; m &= m - 1;
            float cs = __shfl_sync(FULLM, cst0, src);
            float io = __shfl_sync(FULLM, iou0, src);
            int aa = awbase + 2 * src;
            wins_bot(bcv, biv, lane, cs, aa);
            wins_top(tv, lane, io);
        }
        m = mc1;
        while (m) {
            int src = __ffs(m) - 1; m &= m - 1;
            float cs = __shfl_sync(FULLM, cst1, src);
            float io = __shfl_sync(FULLM, iou1, src);
            int aa = awbase + 2 * src + 1;
            wins_bot(bcv, biv, lane, cs, aa);
            wins_top(tv, lane, io);
        }
        if (lane < 10) {
            int pidx = ((b * NG + g) * NSEG + seg) * 10 + lane;
            g_pt[pidx] = tv; g_pc[pidx] = bcv; g_pi[pidx] = biv;
        }
    }
}

// ---------------- K3: merge 336 segment partials per (b,g) ----------------
__global__ void k_sel2() {
    int bg = blockIdx.x;
    int lane = threadIdx.x;
    if (!g_gvalid[bg]) {
        if (lane == 0) { g_dynk[bg] = 0; g_thrC[bg] = -3.0e38f; g_thrI[bg] = -1; }
        return;
    }
    const float* __restrict__ pt = g_pt + (size_t)bg * NSEG * 10;
    const float* __restrict__ pcr = g_pc + (size_t)bg * NSEG * 10;
    const int*   __restrict__ pir = g_pi + (size_t)bg * NSEG * 10;

    float tv = 0.f, bcv = 3.0e38f; int biv = 0x7fffffff;
    float thr_t = 0.f, thr_c = 3.0e38f; int thr_i = 0x7fffffff;
    for (int i = 0; i < NSEG * 10 / 32; i++) {           // 105 batches
        int e = i * 32 + lane;
        float a = pt[e];
        float c = pcr[e];
        int  ix = pir[e];
        // strict-index tie filter: empty (INF, INT_MAX) entries never fire
        unsigned mt = __ballot_sync(FULLM, a > thr_t);
        unsigned mc = __ballot_sync(FULLM, (c < thr_c) || (c == thr_c && ix < thr_i));
        if (mt) {
            do {
                int src = __ffs(mt) - 1; mt &= mt - 1;
                wins_top(tv, lane, __shfl_sync(FULLM, a, src));
            } while (mt);
            thr_t = __shfl_sync(FULLM, tv, 9);
        }
        if (mc) {
            do {
                int src = __ffs(mc) - 1; mc &= mc - 1;
                float cs = __shfl_sync(FULLM, c, src);
                int  ii = __shfl_sync(FULLM, ix, src);
                wins_bot(bcv, biv, lane, cs, ii);
            } while (mc);
            thr_c = __shfl_sync(FULLM, bcv, 9);
            thr_i = __shfl_sync(FULLM, biv, 9);
        }
    }
    float x = (lane < 10) ? tv : 0.f;
    #pragma unroll
    for (int o = 16; o > 0; o >>= 1) x += __shfl_xor_sync(FULLM, x, o);
    int k = (int)x;
    if (k < 1) k = 1;
    if (k > 10) k = 10;
    float thrC = __shfl_sync(FULLM, bcv, k - 1);
    int   thrI = __shfl_sync(FULLM, biv, k - 1);
    if (lane == 0) { g_dynk[bg] = k; g_thrC[bg] = thrC; g_thrI[bg] = thrI; }
}

// ---------------- K5 tail helper: per-anchor fg losses ----------------
__device__ __forceinline__ void tail_loss(
    int b, int a, int t, int mg, float pi,
    const float* __restrict__ o8, const float* __restrict__ o16, const float* __restrict__ o32,
    const float* s_cx, const float* s_cy, const float* s_a1, const float* s_b1,
    const float* s_c1, const float* s_d1s, const int* s_cls,
    float& liou, float& lcls)
{
    float bx = g_bx[t], by = g_by[t];
    float a2 = g_a2[t], b2 = g_b2[t], c2 = g_c2[t], d2s = g_d2s[t];
    float Af = a2 + s_a1[mg], Bf = b2 + s_b1[mg], Cf = c2 + s_c1[mg];
    float dx = bx - s_cx[mg], dy = by - s_cy[mg];
    float den = Af * Bf - Cf * Cf + 1e-8f;
    float rden = __fdividef(1.f, den);
    float t1 = 0.25f * (Af*dy*dy + Bf*dx*dx) * rden;
    float t2 = -0.5f * Cf * dx * dy * rden;
    float t3 = 0.5f * __logf(__fdividef(den, 4.f * s_d1s[mg] * d2s + 1e-8f));
    float bd = fminf(fmaxf(t1 + t2 + t3, 1e-8f), 100.f);
    float q = fminf(fmaxf(1.f - __expf(-bd), 1e-20f), 1.f);
    float ioum = 1.f - q * __frsqrt_rn(q);
    liou += 1.f - ioum;
    const float* src; int hw, i;
    if (a < L0N)      { src = o8;  hw = 16384; i = a; }
    else if (a < L1N) { src = o16; hw = 4096;  i = a - L0N; }
    else              { src = o32; hw = 1024;  i = a - L1N; }
    const float* pc = src + ((size_t)b * 21 + 6) * hw + i;
    int mcls = s_cls[mg];
    #pragma unroll
    for (int c = 0; c < NC; c++) {
        float x = pc[(size_t)c * hw];
        float tg = (c == mcls) ? pi : 0.f;
        lcls += fmaxf(x, 0.f) - x * tg + __logf(1.f + __expf(-fabsf(x)));
    }
}

// ---------------- K5: match resolution (recompute) + loss ----------------
__global__ void k_loss(const float* __restrict__ o8,
                       const float* __restrict__ o16,
                       const float* __restrict__ o32) {
    int b = blockIdx.x / 84;
    int tile = blockIdx.x - b * 84;
    int tid = threadIdx.x;
    int a0 = tile * 256 + 2 * tid;
    int t0 = b * NA + a0;
    __shared__ float s_thrC[NG], s_cx[NG], s_cy[NG], s_hw[NG], s_hh[NG];
    __shared__ float s_a1[NG], s_b1[NG], s_c1[NG], s_ld1[NG], s_d1s[NG];
    __shared__ int   s_thrI[NG], s_k[NG], s_cls[NG];
    if (tid < NG) {
        int gi = b * NG + tid;
        int v = g_gvalid[gi];
        s_thrC[tid] = g_thrC[gi]; s_thrI[tid] = g_thrI[gi]; s_k[tid] = g_dynk[gi];
        s_cx[tid] = v ? g_gcx[gi] : 3.0e9f;
        s_cy[tid] = v ? g_gcy[gi] : 3.0e9f;
        s_hw[tid] = g_ghw[gi]; s_hh[tid] = g_ghh[gi];
        s_a1[tid] = g_ga1[gi]; s_b1[tid] = g_gb1[gi]; s_c1[tid] = g_gc1[gi];
        s_ld1[tid] = g_gld1[gi]; s_d1s[tid] = g_gd1s[gi]; s_cls[tid] = g_gcls[gi];
    }
    __syncthreads();
    float st; int lvlbase, shx, mskx;
    if (a0 < L0N)      { st = 8.f;  lvlbase = 0;    shx = 7; mskx = 127; }
    else if (a0 < L1N) { st = 16.f; lvlbase = L0N;  shx = 6; mskx = 63; }
    else               { st = 32.f; lvlbase = L1N;  shx = 5; mskx = 31; }
    int i0 = a0 - lvlbase;
    float xc0 = ((float)(i0 & mskx) + 0.5f) * st;
    float yc0 = ((float)(i0 >> shx) + 0.5f) * st;
    float xc1 = xc0 + st;
    float rad = 2.5f * st;

    float2 bx01 = *(const float2*)&g_bx[t0];
    float2 by01 = *(const float2*)&g_by[t0];
    float2 A01  = *(const float2*)&g_a2[t0];
    float2 B01  = *(const float2*)&g_b2[t0];
    float2 C01  = *(const float2*)&g_c2[t0];
    float2 S01  = *(const float2*)&g_S[t0];
    float2 ld01 = *(const float2*)&g_ld2[t0];
    float lb0 = ld01.x + LOG4F, lb1 = ld01.y + LOG4F;

    unsigned long long both0 = 0ULL, both1 = 0ULL;
    bool c0 = false, c1 = false;
    #pragma unroll 4
    for (int g = 0; g < NG; g++) {
        float cx = s_cx[g], cy = s_cy[g], hwv = s_hw[g], hh = s_hh[g];
        float dx0 = fabsf(xc0 - cx), dy0 = fabsf(yc0 - cy);
        float dx1 = fabsf(xc1 - cx);
        bool ib0 = (dx0 < hwv) & (dy0 < hh);
        bool ic0 = (dx0 < rad) & (dy0 < rad);
        bool ib1 = (dx1 < hwv) & (dy0 < hh);
        bool ic1 = (dx1 < rad) & (dy0 < rad);
        c0 |= ib0 | ic0; c1 |= ib1 | ic1;
        if (ib0 & ic0) both0 |= (1ULL << g);
        if (ib1 & ic1) both1 |= (1ULL << g);
    }
    float pc0 = c0 ? 0.f : 1e6f;
    float pc1 = c1 ? 0.f : 1e6f;
    unsigned any = __ballot_sync(FULLM, c0 | c1);

    int cnt0 = 0, cnt1 = 0, mg0 = 0, mg1 = 0, mn0 = 0, mn1 = 0;
    bool f0 = false, f1 = false;
    float minc0 = 3.4e38f, minc1 = 3.4e38f, mi0 = 0.f, mi1 = 0.f, ps0 = 0.f, ps1 = 0.f;
    if (any) {
        float iou0, cst0, iou1, cst1;
        for (int g = 0; g < NG; g++) {
            if (s_k[g] == 0) continue;      // invalid GT
            float thrC = s_thrC[g]; int thrI = s_thrI[g];
            if (c0) {
                float lc = g_lc[s_cls[g] * BA + t0];
                float pb = ((both0 >> g) & 1ULL) ? 0.f : 1e5f;
                pair_cost(s_a1[g], s_b1[g], s_c1[g], s_cx[g], s_cy[g], s_ld1[g],
                          A01.x, B01.x, C01.x, bx01.x, by01.x, lb0, S01.x, lc, pb, pc0,
                          iou0, cst0);
                bool m0 = (cst0 < thrC) || (cst0 == thrC && a0 <= thrI);
                if (m0) { cnt0++; if (!f0) { mg0 = g; f0 = true; } ps0 += iou0; }
                if (cst0 < minc0) { minc0 = cst0; mn0 = g; mi0 = iou0; }
            }
            if (c1) {
                float lc = g_lc[s_cls[g] * BA + t0 + 1];
                float pb = ((both1 >> g) & 1ULL) ? 0.f : 1e5f;
                pair_cost(s_a1[g], s_b1[g], s_c1[g], s_cx[g], s_cy[g], s_ld1[g],
                          A01.y, B01.y, C01.y, bx01.y, by01.y, lb1, S01.y, lc, pb, pc1,
                          iou1, cst1);
                bool m1 = (cst1 < thrC) || (cst1 == thrC && a0 + 1 <= thrI);
                if (m1) { cnt1++; if (!f1) { mg1 = g; f1 = true; } ps1 += iou1; }
                if (cst1 < minc1) { minc1 = cst1; mn1 = g; mi1 = iou1; }
            }
        }
    }
    float pi0 = ps0, pi1 = ps1;
    if (cnt0 > 1) { mg0 = mn0; pi0 = mi0; }
    if (cnt1 > 1) { mg1 = mn1; pi1 = mi1; }
    bool fg0 = cnt0 > 0, fg1 = cnt1 > 0;
    float2 ob = *(const float2*)&g_obj[t0];
    float fo = (fg0 ? 1.f : 0.f) + (fg1 ? 1.f : 0.f);
    float lobj = fmaxf(ob.x, 0.f) - ob.x * (fg0 ? 1.f : 0.f) + __logf(1.f + __expf(-fabsf(ob.x)))
               + fmaxf(ob.y, 0.f) - ob.y * (fg1 ? 1.f : 0.f) + __logf(1.f + __expf(-fabsf(ob.y)));
    float liou = 0.f, lcls = 0.f;
    if (fg0) tail_loss(b, a0,     t0,     mg0, pi0, o8, o16, o32, s_cx, s_cy, s_a1, s_b1, s_c1, s_d1s, s_cls, liou, lcls);
    if (fg1) tail_loss(b, a0 + 1, t0 + 1, mg1, pi1, o8, o16, o32, s_cx, s_cy, s_a1, s_b1, s_c1, s_d1s, s_cls, liou, lcls);

    #pragma unroll
    for (int o = 16; o > 0; o >>= 1) {
        liou += __shfl_down_sync(FULLM, liou, o);
        lobj += __shfl_down_sync(FULLM, lobj, o);
        lcls += __shfl_down_sync(FULLM, lcls, o);
        fo   += __shfl_down_sync(FULLM, fo, o);
    }
    __shared__ float rs[4][4];
    int w = tid >> 5, lane = tid & 31;
    if (lane == 0) { rs[0][w] = liou; rs[1][w] = lobj; rs[2][w] = lcls; rs[3][w] = fo; }
    __syncthreads();
    if (tid == 0) {
        atomicAdd(&g_acc[0], rs[0][0] + rs[0][1] + rs[0][2] + rs[0][3]);
        atomicAdd(&g_acc[1], rs[1][0] + rs[1][1] + rs[1][2] + rs[1][3]);
        atomicAdd(&g_acc[2], rs[2][0] + rs[2][1] + rs[2][2] + rs[2][3]);
        atomicAdd(&g_acc[3], rs[3][0] + rs[3][1] + rs[3][2] + rs[3][3]);
    }
}

// ---------------- K6: finalize ----------------
__global__ void k_final(float* __restrict__ out, int n) {
    if (threadIdx.x == 0) {
        float nfg = g_acc[3];
        float nf = fmaxf(nfg, 1.f);
        float liou = g_acc[0] / nf;
        float lobj = g_acc[1] / nf;
        float lcls = g_acc[2] / nf;
        float li5 = 5.f * liou;
        float loss = li5 + lobj + lcls;
        if (n > 0) out[0] = loss;
        if (n > 1) out[1] = li5;
        if (n > 2) out[2] = lobj;
        if (n > 3) out[3] = lcls;
        if (n > 4) out[4] = 0.f;
        if (n > 5) out[5] = nfg / fmaxf(g_acc[4], 1.f);
        for (int i = 6; i < n; i++) out[i] = 0.f;
    }
}

// ---------------- launch ----------------
extern "C" void kernel_launch(void* const* d_in, const int* in_sizes, int n_in,
                              void* d_out, int out_size) {
    const float* o8     = (const float*)d_in[0];
    const float* o16    = (const float*)d_in[1];
    const float* o32    = (const float*)d_in[2];
    const float* labels = (const float*)d_in[3];
    float* out = (float*)d_out;

    k_gt<<<1, 512>>>(labels);
    k_decode<<<BA / 128, 128>>>(o8, o16, o32);
    k_costred<<<NB * 84, 128>>>();
    k_sel2<<<NBG, 32>>>();
    k_loss<<<NB * 84, 128>>>(o8, o16, o32);
    k_final<<<1, 32>>>(out, out_size);
}

// round 9
// speedup vs baseline: 3.6469x; 3.6469x over previous
#include <cuda_runtime.h>
#include <math.h>

#define NB 8
#define NA 21504
#define NG 60
#define NC 15
#define BA (NB*NA)
#define NBG (NB*NG)
#define L0N 16384
#define L1N 20480
#define LOG4F 1.3862943611198906f
#define FULLM 0xffffffffu
#define NSEG 12     // 12 segments of 1792 anchors per (b,g) row

// ---------------- static device scratch ----------------
__device__ float g_bx[BA], g_by[BA];
__device__ float g_a2[BA], g_b2[BA], g_c2[BA], g_d2s[BA], g_ld2[BA];
__device__ float g_obj[BA], g_S[BA];
__device__ float g_lc[NC*BA];                 // [c][b*A+a]
__device__ float2 g_ic[(size_t)NBG*NA];       // {iou, cost} per [(b*G+g)][a]
__device__ float g_gcx[NBG], g_gcy[NBG], g_ghw[NBG], g_ghh[NBG];
__device__ float g_ga1[NBG], g_gb1[NBG], g_gc1[NBG], g_gd1s[NBG], g_gld1[NBG];
__device__ int   g_gcls[NBG], g_gvalid[NBG];
__device__ int   g_dynk[NBG];
__device__ float g_thrC[NBG];
__device__ int   g_thrI[NBG];
__device__ float g_pt[NBG*NSEG*10];           // partial top-iou lists
__device__ float g_pc[NBG*NSEG*10];           // partial bot-cost lists
__device__ int   g_pi[NBG*NSEG*10];
__device__ float g_acc[5];   // 0: sum(1-iou_m), 1: bce_obj, 2: bce_cls, 3: num_fg, 4: num_gts

// ---------------- K1b: GT prep + zero accumulators (1 block) ----------------
__global__ void k_gt(const float* __restrict__ labels) {
    int t = threadIdx.x;
    if (t < 5) g_acc[t] = 0.f;
    __syncthreads();
    if (t >= NBG) return;
    const float* L = labels + (size_t)t * 6;
    float l0 = L[0], l1 = L[1], l2 = L[2], l3 = L[3], l4 = L[4], l5 = L[5];
    float sum = l0 + l1 + l2 + l3 + l4 + l5;
    int valid = (sum > 0.f) ? 1 : 0;
    float sn, cs; __sincosf(l5, &sn, &cs);
    float w2 = l3*l3/12.0f, h2 = l4*l4/12.0f;
    float a1 = w2*cs*cs + h2*sn*sn;
    float b1 = w2*sn*sn + h2*cs*cs;
    float c1 = (w2 - h2) * cs * sn;
    float d1 = fmaxf(a1*b1 - c1*c1, 0.f);
    float d1s = d1 * __frsqrt_rn(fmaxf(d1, 1e-30f));
    g_gcx[t] = l1; g_gcy[t] = l2;
    g_ghw[t] = 0.5f * l3; g_ghh[t] = 0.5f * l4;
    g_ga1[t] = a1; g_gb1[t] = b1; g_gc1[t] = c1;
    g_gd1s[t] = d1s;
    g_gld1[t] = __logf(fmaxf(d1s, 1e-35f));
    g_gcls[t] = (int)l0;
    g_gvalid[t] = valid;
    if (valid) atomicAdd(&g_acc[4], 1.f);
}

// ---------------- K1: decode anchors ----------------
__global__ void k_decode(const float* __restrict__ o8,
                         const float* __restrict__ o16,
                         const float* __restrict__ o32) {
    int t = blockIdx.x * blockDim.x + threadIdx.x;
    if (t >= BA) return;
    int b = t / NA;
    int a = t - b * NA;
    const float* src; int hw, i; float st; int gx, gy;
    if (a < L0N)       { src = o8;  hw = 16384; i = a;        st = 8.f;  gx = i & 127; gy = i >> 7; }
    else if (a < L1N)  { src = o16; hw = 4096;  i = a - L0N;  st = 16.f; gx = i & 63;  gy = i >> 6; }
    else               { src = o32; hw = 1024;  i = a - L1N;  st = 32.f; gx = i & 31;  gy = i >> 5; }
    const float* p0 = src + (size_t)b * 21 * hw + i;
    float r0 = p0[0], r1 = p0[hw], r2 = p0[2*hw], r3 = p0[3*hw], r4 = p0[4*hw], r5 = p0[5*hw];
    float bx = (r0 + (float)gx) * st;
    float by = (r1 + (float)gy) * st;
    float bw = __expf(r2) * st;
    float bh = __expf(r3) * st;
    float sn, cs; __sincosf(r4, &sn, &cs);
    float w2 = bw * bw / 12.0f, h2 = bh * bh / 12.0f;
    float a2 = w2*cs*cs + h2*sn*sn;
    float b2 = w2*sn*sn + h2*cs*cs;
    float c2 = (w2 - h2) * cs * sn;
    float d2 = fmaxf(a2*b2 - c2*c2, 0.f);
    float d2s = d2 * __frsqrt_rn(fmaxf(d2, 1e-30f));
    g_bx[t] = bx; g_by[t] = by;
    g_a2[t] = a2; g_b2[t] = b2; g_c2[t] = c2;
    g_d2s[t] = d2s;
    g_ld2[t] = __logf(fmaxf(d2s, 1e-35f));
    g_obj[t] = r5;
    float so = __fdividef(1.f, 1.f + __expf(-r5));
    float S = 0.f;
    #pragma unroll
    for (int c = 0; c < NC; c++) {
        float x = p0[(6 + c) * hw];
        float sc = __fdividef(1.f, 1.f + __expf(-x));
        float q = sc * so;
        float p = q * __frsqrt_rn(fmaxf(q, 1e-30f));
        p = fminf(fmaxf(p, 1e-7f), 1.f - 1e-7f);
        float lg = __logf(1.f - p);
        float lp = __logf(p);
        S -= lg;
        g_lc[c * BA + t] = lg - lp;
    }
    g_S[t] = S;
}

// ---------------- K2: dense ious + cost (anchors 2i,2i+1 per thread) ----------------
__global__ void k_cost() {
    int b = blockIdx.x / 84;
    int tile = blockIdx.x - b * 84;
    int tid = threadIdx.x;
    int a0 = tile * 256 + 2 * tid;          // even; a1 = a0+1 same level, same row
    int t0 = b * NA + a0;
    __shared__ float s_cx[NG], s_cy[NG], s_hw[NG], s_hh[NG];
    __shared__ float s_a1[NG], s_b1[NG], s_c1[NG], s_ld1[NG];
    __shared__ int   s_cls[NG], s_val[NG];
    if (tid < NG) {
        int gi = b * NG + tid;
        int v = g_gvalid[gi];
        s_val[tid] = v;
        s_cx[tid] = v ? g_gcx[gi] : 3.0e9f;
        s_cy[tid] = v ? g_gcy[gi] : 3.0e9f;
        s_hw[tid] = g_ghw[gi]; s_hh[tid] = g_ghh[gi];
        s_a1[tid] = g_ga1[gi]; s_b1[tid] = g_gb1[gi];
        s_c1[tid] = g_gc1[gi]; s_ld1[tid] = g_gld1[gi];
        s_cls[tid] = g_gcls[gi];
    }
    __syncthreads();
    float st; int lvlbase, shx, mskx;
    if (a0 < L0N)      { st = 8.f;  lvlbase = 0;    shx = 7; mskx = 127; }
    else if (a0 < L1N) { st = 16.f; lvlbase = L0N;  shx = 6; mskx = 63; }
    else               { st = 32.f; lvlbase = L1N;  shx = 5; mskx = 31; }
    int i0 = a0 - lvlbase;
    float xc0 = ((float)(i0 & mskx) + 0.5f) * st;
    float yc0 = ((float)(i0 >> shx) + 0.5f) * st;
    float xc1 = xc0 + st;
    float rad = 2.5f * st;

    float2 bx01 = *(const float2*)&g_bx[t0];
    float2 by01 = *(const float2*)&g_by[t0];
    float2 A01  = *(const float2*)&g_a2[t0];
    float2 B01  = *(const float2*)&g_b2[t0];
    float2 C01  = *(const float2*)&g_c2[t0];
    float2 S01  = *(const float2*)&g_S[t0];
    float2 ld01 = *(const float2*)&g_ld2[t0];
    float lb0 = ld01.x + LOG4F, lb1 = ld01.y + LOG4F;

    unsigned long long both0 = 0ULL, both1 = 0ULL;
    bool c0 = false, c1 = false;
    #pragma unroll 4
    for (int g = 0; g < NG; g++) {
        float cx = s_cx[g], cy = s_cy[g], hwv = s_hw[g], hh = s_hh[g];
        float dx0 = fabsf(xc0 - cx), dy0 = fabsf(yc0 - cy);
        float dx1 = fabsf(xc1 - cx);
        bool ib0 = (dx0 < hwv) & (dy0 < hh);
        bool ic0 = (dx0 < rad) & (dy0 < rad);
        bool ib1 = (dx1 < hwv) & (dy0 < hh);
        bool ic1 = (dx1 < rad) & (dy0 < rad);
        c0 |= ib0 | ic0; c1 |= ib1 | ic1;
        if (ib0 & ic0) both0 |= (1ULL << g);
        if (ib1 & ic1) both1 |= (1ULL << g);
    }
    float pc0 = c0 ? 0.f : 1e6f;
    float pc1 = c1 ? 0.f : 1e6f;
    size_t rowbase = (size_t)b * NG * NA + a0;

    for (int g = 0; g < NG; g++) {
        float4* dst = (float4*)(g_ic + rowbase + (size_t)g * NA);
        if (!s_val[g]) {
            *dst = make_float4(0.f, 2e9f, 0.f, 2e9f);
            continue;
        }
        float ga = s_a1[g], gb = s_b1[g], gc = s_c1[g];
        float cx = s_cx[g], cy = s_cy[g];
        float lg1 = s_ld1[g];
        float2 lc = *(const float2*)&g_lc[s_cls[g] * BA + t0];
        float4 o;
        {
            float Af = ga + A01.x, Bf = gb + B01.x, Cf = gc + C01.x;
            float dx = cx - bx01.x, dy = cy - by01.x;
            float den = Af * Bf - Cf * Cf + 1e-8f;
            float rden = __fdividef(1.f, den);
            float t1 = 0.25f * (Af*dy*dy + Bf*dx*dx) * rden;
            float t2 = -0.5f * Cf * dx * dy * rden;
            float t3 = 0.5f * (__logf(den) - (lg1 + lb0));
            float bd = fminf(fmaxf(t1 + t2 + t3, 1e-8f), 100.f);
            float q = fminf(fmaxf(1.f - __expf(-bd), 1e-20f), 1.f);
            float iou = 1.f - q * __frsqrt_rn(q);
            float pb = ((both0 >> g) & 1ULL) ? 0.f : 1e5f;
            o.x = iou;
            o.y = fmaf(-3.f, __logf(iou + 1e-8f), S01.x + lc.x + pb + pc0);
        }
        {
            float Af = ga + A01.y, Bf = gb + B01.y, Cf = gc + C01.y;
            float dx = cx - bx01.y, dy = cy - by01.y;
            float den = Af * Bf - Cf * Cf + 1e-8f;
            float rden = __fdividef(1.f, den);
            float t1 = 0.25f * (Af*dy*dy + Bf*dx*dx) * rden;
            float t2 = -0.5f * Cf * dx * dy * rden;
            float t3 = 0.5f * (__logf(den) - (lg1 + lb1));
            float bd = fminf(fmaxf(t1 + t2 + t3, 1e-8f), 100.f);
            float q = fminf(fmaxf(1.f - __expf(-bd), 1e-20f), 1.f);
            float iou = 1.f - q * __frsqrt_rn(q);
            float pb = ((both1 >> g) & 1ULL) ? 0.f : 1e5f;
            o.z = iou;
            o.w = fmaf(-3.f, __logf(iou + 1e-8f), S01.y + lc.y + pb + pc1);
        }
        *dst = o;
    }
}

// ---------------- selection helpers ----------------
__device__ __forceinline__ bool pless(float c1, int i1, float c2, int i2) {
    return (c1 < c2) || (c1 == c2 && i1 < i2);
}
// private, statically-indexed sorted lists (registers; no dynamic indexing anywhere)
__device__ __forceinline__ void pins_top(float (&t)[10], float e) {
    if (e > t[9]) {
        t[9] = e;
        #pragma unroll
        for (int j = 9; j >= 1; j--) {
            float hi = fmaxf(t[j-1], t[j]);
            float lo = fminf(t[j-1], t[j]);
            t[j-1] = hi; t[j] = lo;
        }
    }
}
__device__ __forceinline__ void pins_bot(float (&bc)[10], int (&bi)[10], float c, int i) {
    if (pless(c, i, bc[9], bi[9])) {
        bc[9] = c; bi[9] = i;
        #pragma unroll
        for (int j = 9; j >= 1; j--) {
            if (pless(bc[j], bi[j], bc[j-1], bi[j-1])) {
                float tc = bc[j]; bc[j] = bc[j-1]; bc[j-1] = tc;
                int ti = bi[j]; bi[j] = bi[j-1]; bi[j-1] = ti;
            }
        }
    }
}
// warp-distributed insert (lanes 0..9 hold list)
__device__ __forceinline__ void wins_top(float& tv, int lane, float c) {
    unsigned bm = __ballot_sync(FULLM, (lane < 10) && (c > tv)) & 0x3FFu;
    if (bm) {
        int p = __ffs(bm) - 1;
        float up = __shfl_up_sync(FULLM, tv, 1);
        if (lane < 10 && lane >= p) tv = (lane == p) ? c : up;
    }
}
__device__ __forceinline__ void wins_bot(float& bcv, int& biv, int lane, float c, int i) {
    unsigned bm = __ballot_sync(FULLM, (lane < 10) && pless(c, i, bcv, biv)) & 0x3FFu;
    if (bm) {
        int p = __ffs(bm) - 1;
        float uc = __shfl_up_sync(FULLM, bcv, 1);
        int   ui = __shfl_up_sync(FULLM, biv, 1);
        if (lane < 10 && lane >= p) { bcv = (lane == p) ? c : uc; biv = (lane == p) ? i : ui; }
    }
}

// ---------------- K3a: per-(b,g,segment) partials via private register lists ----------------
__global__ void k_sel1() {
    int bg = blockIdx.x / 3;
    int part = blockIdx.x - bg * 3;
    if (!g_gvalid[bg]) return;
    int w = threadIdx.x >> 5, lane = threadIdx.x & 31;
    int seg = part * 4 + w;                 // 0..11
    const float4* __restrict__ row4 = (const float4*)(g_ic + (size_t)bg * NA);
    int base = seg * 896;                   // 896 f4 = 1792 anchors per segment

    float t[10]; float bc[10]; int bi[10];
    #pragma unroll
    for (int j = 0; j < 10; j++) { t[j] = 0.f; bc[j] = 3.0e38f; bi[j] = 0x7fffffff; }

    #pragma unroll 1
    for (int s = 0; s < 28; s++) {
        int fi = base + s * 32 + lane;
        float4 v = row4[fi];
        int a0 = fi * 2;
        float e0 = (v.y < 1e6f) ? v.x : 0.f;   // cand <=> cost < 1e6 (penalty separation)
        float e1 = (v.w < 1e6f) ? v.z : 0.f;
        pins_top(t, e0);
        pins_top(t, e1);
        pins_bot(bc, bi, v.y, a0);
        pins_bot(bc, bi, v.w, a0 + 1);
    }

    // one-time warp merge of 32 private lists -> distributed list in lanes 0..9
    float tv = 0.f; float bcv = 3.0e38f; int biv = 0x7fffffff;
    #pragma unroll
    for (int j = 0; j < 10; j++) {
        float thr = __shfl_sync(FULLM, tv, 9);
        unsigned m = __ballot_sync(FULLM, t[j] > thr);
        while (m) {
            int src = __ffs(m) - 1; m &= m - 1;
            wins_top(tv, lane, __shfl_sync(FULLM, t[j], src));
        }
        float tc = __shfl_sync(FULLM, bcv, 9);
        int   ti = __shfl_sync(FULLM, biv, 9);
        m = __ballot_sync(FULLM, pless(bc[j], bi[j], tc, ti));
        while (m) {
            int src = __ffs(m) - 1; m &= m - 1;
            float c = __shfl_sync(FULLM, bc[j], src);
            int  ii = __shfl_sync(FULLM, bi[j], src);
            wins_bot(bcv, biv, lane, c, ii);
        }
    }
    if (lane < 10) {
        int o = (bg * NSEG + seg) * 10 + lane;
        g_pt[o] = tv; g_pc[o] = bcv; g_pi[o] = biv;
    }
}

// ---------------- K3b: merge 12 segment partials per (b,g) ----------------
__global__ void k_sel2() {
    int bg = blockIdx.x;
    int lane = threadIdx.x;
    if (!g_gvalid[bg]) {
        if (lane == 0) { g_dynk[bg] = 0; g_thrC[bg] = -3.0e38f; g_thrI[bg] = -1; }
        return;
    }
    const float* __restrict__ pt = g_pt + (size_t)bg * NSEG * 10;
    const float* __restrict__ pcr = g_pc + (size_t)bg * NSEG * 10;
    const int*   __restrict__ pir = g_pi + (size_t)bg * NSEG * 10;

    float tv = 0.f, bcv = 3.0e38f; int biv = 0x7fffffff;
    float thr_t = 0.f, thr_c = 3.0e38f; int thr_i = 0x7fffffff;
    #pragma unroll
    for (int i = 0; i < 4; i++) {           // 120 entries in 4 batches of 32
        int e = i * 32 + lane;
        bool ok = e < NSEG * 10;
        float a = ok ? pt[e]  : 0.f;
        float c = ok ? pcr[e] : 3.0e38f;
        int  ix = ok ? pir[e] : 0x7fffffff;
        unsigned mt = __ballot_sync(FULLM, a > thr_t);
        unsigned mc = __ballot_sync(FULLM, (c < thr_c) || (c == thr_c && ix < thr_i));
        while (mt) {
            int src = __ffs(mt) - 1; mt &= mt - 1;
            wins_top(tv, lane, __shfl_sync(FULLM, a, src));
        }
        thr_t = __shfl_sync(FULLM, tv, 9);
        while (mc) {
            int src = __ffs(mc) - 1; mc &= mc - 1;
            float cs = __shfl_sync(FULLM, c, src);
            int  ii = __shfl_sync(FULLM, ix, src);
            wins_bot(bcv, biv, lane, cs, ii);
        }
        thr_c = __shfl_sync(FULLM, bcv, 9);
        thr_i = __shfl_sync(FULLM, biv, 9);
    }
    float x = (lane < 10) ? tv : 0.f;
    #pragma unroll
    for (int o = 16; o > 0; o >>= 1) x += __shfl_xor_sync(FULLM, x, o);
    int k = (int)x;
    if (k < 1) k = 1;
    if (k > 10) k = 10;
    float thrC = __shfl_sync(FULLM, bcv, k - 1);
    int   thrI = __shfl_sync(FULLM, biv, k - 1);
    if (lane == 0) { g_dynk[bg] = k; g_thrC[bg] = thrC; g_thrI[bg] = thrI; }
}

// ---------------- K5 tail helper: per-anchor fg losses ----------------
__device__ __forceinline__ void tail_loss(
    int b, int a, int t, int mg, float pi,
    const float* __restrict__ o8, const float* __restrict__ o16, const float* __restrict__ o32,
    const float* s_cx, const float* s_cy, const float* s_a1, const float* s_b1,
    const float* s_c1, const float* s_d1s, const int* s_cls,
    float& liou, float& lcls)
{
    float bx = g_bx[t], by = g_by[t];
    float a2 = g_a2[t], b2 = g_b2[t], c2 = g_c2[t], d2s = g_d2s[t];
    float Af = a2 + s_a1[mg], Bf = b2 + s_b1[mg], Cf = c2 + s_c1[mg];
    float dx = bx - s_cx[mg], dy = by - s_cy[mg];
    float den = Af * Bf - Cf * Cf + 1e-8f;
    float rden = __fdividef(1.f, den);
    float t1 = 0.25f * (Af*dy*dy + Bf*dx*dx) * rden;
    float t2 = -0.5f * Cf * dx * dy * rden;
    float t3 = 0.5f * __logf(__fdividef(den, 4.f * s_d1s[mg] * d2s + 1e-8f));
    float bd = fminf(fmaxf(t1 + t2 + t3, 1e-8f), 100.f);
    float q = fminf(fmaxf(1.f - __expf(-bd), 1e-20f), 1.f);
    float ioum = 1.f - q * __frsqrt_rn(q);
    liou += 1.f - ioum;
    const float* src; int hw, i;
    if (a < L0N)      { src = o8;  hw = 16384; i = a; }
    else if (a < L1N) { src = o16; hw = 4096;  i = a - L0N; }
    else              { src = o32; hw = 1024;  i = a - L1N; }
    const float* pc = src + ((size_t)b * 21 + 6) * hw + i;
    int mcls = s_cls[mg];
    #pragma unroll
    for (int c = 0; c < NC; c++) {
        float x = pc[(size_t)c * hw];
        float tg = (c == mcls) ? pi : 0.f;
        lcls += fmaxf(x, 0.f) - x * tg + __logf(1.f + __expf(-fabsf(x)));
    }
}

// ---------------- K5: match resolution + loss (2 anchors / thread) ----------------
__global__ void k_loss(const float* __restrict__ o8,
                       const float* __restrict__ o16,
                       const float* __restrict__ o32) {
    int b = blockIdx.x / 84;
    int tile = blockIdx.x - b * 84;
    int a0 = tile * 256 + 2 * threadIdx.x;
    int t0 = b * NA + a0;
    __shared__ float s_thrC[NG], s_cx[NG], s_cy[NG], s_a1[NG], s_b1[NG], s_c1[NG], s_d1s[NG];
    __shared__ int   s_thrI[NG], s_k[NG], s_cls[NG];
    if (threadIdx.x < NG) {
        int gi = b * NG + threadIdx.x;
        s_thrC[threadIdx.x] = g_thrC[gi]; s_thrI[threadIdx.x] = g_thrI[gi]; s_k[threadIdx.x] = g_dynk[gi];
        s_cx[threadIdx.x] = g_gcx[gi]; s_cy[threadIdx.x] = g_gcy[gi];
        s_a1[threadIdx.x] = g_ga1[gi]; s_b1[threadIdx.x] = g_gb1[gi]; s_c1[threadIdx.x] = g_gc1[gi];
        s_d1s[threadIdx.x] = g_gd1s[gi]; s_cls[threadIdx.x] = g_gcls[gi];
    }
    __syncthreads();
    const float4* __restrict__ col4 = (const float4*)(g_ic + (size_t)b * NG * NA + a0);
    int cnt0 = 0, cnt1 = 0, mg0 = 0, mg1 = 0, mn0 = 0, mn1 = 0;
    bool f0 = false, f1 = false;
    float minc0 = 3.4e38f, minc1 = 3.4e38f, mi0 = 0.f, mi1 = 0.f, ps0 = 0.f, ps1 = 0.f;
    #pragma unroll 4
    for (int g = 0; g < NG; g++) {
        float4 ic = col4[(size_t)g * (NA/2)];
        bool kk = s_k[g] > 0;
        bool m0 = kk && ((ic.y < s_thrC[g]) || (ic.y == s_thrC[g] && a0 <= s_thrI[g]));
        bool m1 = kk && ((ic.w < s_thrC[g]) || (ic.w == s_thrC[g] && a0 + 1 <= s_thrI[g]));
        if (m0) { cnt0++; if (!f0) { mg0 = g; f0 = true; } ps0 += ic.x; }
        if (m1) { cnt1++; if (!f1) { mg1 = g; f1 = true; } ps1 += ic.z; }
        if (ic.y < minc0) { minc0 = ic.y; mn0 = g; mi0 = ic.x; }
        if (ic.w < minc1) { minc1 = ic.w; mn1 = g; mi1 = ic.z; }
    }
    float pi0 = ps0, pi1 = ps1;
    if (cnt0 > 1) { mg0 = mn0; pi0 = mi0; }
    if (cnt1 > 1) { mg1 = mn1; pi1 = mi1; }
    bool fg0 = cnt0 > 0, fg1 = cnt1 > 0;
    float2 ob = *(const float2*)&g_obj[t0];
    float fo = (fg0 ? 1.f : 0.f) + (fg1 ? 1.f : 0.f);
    float lobj = fmaxf(ob.x, 0.f) - ob.x * (fg0 ? 1.f : 0.f) + __logf(1.f + __expf(-fabsf(ob.x)))
               + fmaxf(ob.y, 0.f) - ob.y * (fg1 ? 1.f : 0.f) + __logf(1.f + __expf(-fabsf(ob.y)));
    float liou = 0.f, lcls = 0.f;
    if (fg0) tail_loss(b, a0,     t0,     mg0, pi0, o8, o16, o32, s_cx, s_cy, s_a1, s_b1, s_c1, s_d1s, s_cls, liou, lcls);
    if (fg1) tail_loss(b, a0 + 1, t0 + 1, mg1, pi1, o8, o16, o32, s_cx, s_cy, s_a1, s_b1, s_c1, s_d1s, s_cls, liou, lcls);

    #pragma unroll
    for (int o = 16; o > 0; o >>= 1) {
        liou += __shfl_down_sync(FULLM, liou, o);
        lobj += __shfl_down_sync(FULLM, lobj, o);
        lcls += __shfl_down_sync(FULLM, lcls, o);
        fo   += __shfl_down_sync(FULLM, fo, o);
    }
    __shared__ float rs[4][4];
    int w = threadIdx.x >> 5, lane = threadIdx.x & 31;
    if (lane == 0) { rs[0][w] = liou; rs[1][w] = lobj; rs[2][w] = lcls; rs[3][w] = fo; }
    __syncthreads();
    if (threadIdx.x == 0) {
        atomicAdd(&g_acc[0], rs[0][0] + rs[0][1] + rs[0][2] + rs[0][3]);
        atomicAdd(&g_acc[1], rs[1][0] + rs[1][1] + rs[1][2] + rs[1][3]);
        atomicAdd(&g_acc[2], rs[2][0] + rs[2][1] + rs[2][2] + rs[2][3]);
        atomicAdd(&g_acc[3], rs[3][0] + rs[3][1] + rs[3][2] + rs[3][3]);
    }
}

// ---------------- K6: finalize ----------------
__global__ void k_final(float* __restrict__ out, int n) {
    if (threadIdx.x == 0) {
        float nfg = g_acc[3];
        float nf = fmaxf(nfg, 1.f);
        float liou = g_acc[0] / nf;
        float lobj = g_acc[1] / nf;
        float lcls = g_acc[2] / nf;
        float li5 = 5.f * liou;
        float loss = li5 + lobj + lcls;
        if (n > 0) out[0] = loss;
        if (n > 1) out[1] = li5;
        if (n > 2) out[2] = lobj;
        if (n > 3) out[3] = lcls;
        if (n > 4) out[4] = 0.f;
        if (n > 5) out[5] = nfg / fmaxf(g_acc[4], 1.f);
        for (int i = 6; i < n; i++) out[i] = 0.f;
    }
}

// ---------------- launch ----------------
extern "C" void kernel_launch(void* const* d_in, const int* in_sizes, int n_in,
                              void* d_out, int out_size) {
    const float* o8     = (const float*)d_in[0];
    const float* o16    = (const float*)d_in[1];
    const float* o32    = (const float*)d_in[2];
    const float* labels = (const float*)d_in[3];
    float* out = (float*)d_out;

    k_gt<<<1, 512>>>(labels);
    k_decode<<<BA / 128, 128>>>(o8, o16, o32);
    k_cost<<<NB * 84, 128>>>();
    k_sel1<<<NBG * 3, 128>>>();
    k_sel2<<<NBG, 32>>>();
    k_loss<<<NB * 84, 128>>>(o8, o16, o32);
    k_final<<<1, 32>>>(out, out_size);
}

// round 10
// speedup vs baseline: 3.9178x; 1.0743x over previous
#include <cuda_runtime.h>
#include <math.h>

#define NB 8
#define NA 21504
#define NG 60
#define NC 15
#define BA (NB*NA)
#define NBG (NB*NG)
#define L0N 16384
#define L1N 20480
#define LOG4F 1.3862943611198906f
#define FULLM 0xffffffffu
#define NSEG 16     // 16 segments of 1344 anchors per (b,g) row

// ---------------- static device scratch ----------------
__device__ float g_bx[BA], g_by[BA];
__device__ float g_a2[BA], g_b2[BA], g_c2[BA], g_d2s[BA], g_ld2[BA];
__device__ float g_obj[BA], g_S[BA];
__device__ float g_lc[NC*BA];                 // [c][b*A+a]
__device__ float2 g_ic[(size_t)NBG*NA];       // {iou, cost} per [(b*G+g)][a]
__device__ float g_gcx[NBG], g_gcy[NBG], g_ghw[NBG], g_ghh[NBG];
__device__ float g_ga1[NBG], g_gb1[NBG], g_gc1[NBG], g_gd1s[NBG], g_gld1[NBG];
__device__ int   g_gcls[NBG], g_gvalid[NBG];
__device__ int   g_dynk[NBG];
__device__ float g_thrC[NBG];
__device__ int   g_thrI[NBG];
__device__ float g_pt[NBG*NSEG*10];           // partial top-iou lists
__device__ float g_pc[NBG*NSEG*10];           // partial bot-cost lists
__device__ int   g_pi[NBG*NSEG*10];
__device__ float g_acc[5];   // 0: sum(1-iou_m), 1: bce_obj, 2: bce_cls, 3: num_fg, 4: num_gts

// ---------------- K1b: GT prep + zero accumulators (1 block) ----------------
__global__ void k_gt(const float* __restrict__ labels) {
    int t = threadIdx.x;
    if (t < 5) g_acc[t] = 0.f;
    __syncthreads();
    if (t >= NBG) return;
    const float* L = labels + (size_t)t * 6;
    float l0 = L[0], l1 = L[1], l2 = L[2], l3 = L[3], l4 = L[4], l5 = L[5];
    float sum = l0 + l1 + l2 + l3 + l4 + l5;
    int valid = (sum > 0.f) ? 1 : 0;
    float sn, cs; __sincosf(l5, &sn, &cs);
    float w2 = l3*l3/12.0f, h2 = l4*l4/12.0f;
    float a1 = w2*cs*cs + h2*sn*sn;
    float b1 = w2*sn*sn + h2*cs*cs;
    float c1 = (w2 - h2) * cs * sn;
    float d1 = fmaxf(a1*b1 - c1*c1, 0.f);
    float d1s = d1 * __frsqrt_rn(fmaxf(d1, 1e-30f));
    g_gcx[t] = l1; g_gcy[t] = l2;
    g_ghw[t] = 0.5f * l3; g_ghh[t] = 0.5f * l4;
    g_ga1[t] = a1; g_gb1[t] = b1; g_gc1[t] = c1;
    g_gd1s[t] = d1s;
    g_gld1[t] = __logf(fmaxf(d1s, 1e-35f));
    g_gcls[t] = (int)l0;
    g_gvalid[t] = valid;
    if (valid) atomicAdd(&g_acc[4], 1.f);
}

// ---------------- K1: decode anchors ----------------
__global__ void k_decode(const float* __restrict__ o8,
                         const float* __restrict__ o16,
                         const float* __restrict__ o32) {
    int t = blockIdx.x * blockDim.x + threadIdx.x;
    if (t >= BA) return;
    int b = t / NA;
    int a = t - b * NA;
    const float* src; int hw, i; float st; int gx, gy;
    if (a < L0N)       { src = o8;  hw = 16384; i = a;        st = 8.f;  gx = i & 127; gy = i >> 7; }
    else if (a < L1N)  { src = o16; hw = 4096;  i = a - L0N;  st = 16.f; gx = i & 63;  gy = i >> 6; }
    else               { src = o32; hw = 1024;  i = a - L1N;  st = 32.f; gx = i & 31;  gy = i >> 5; }
    const float* p0 = src + (size_t)b * 21 * hw + i;
    float r0 = p0[0], r1 = p0[hw], r2 = p0[2*hw], r3 = p0[3*hw], r4 = p0[4*hw], r5 = p0[5*hw];
    float bx = (r0 + (float)gx) * st;
    float by = (r1 + (float)gy) * st;
    float bw = __expf(r2) * st;
    float bh = __expf(r3) * st;
    float sn, cs; __sincosf(r4, &sn, &cs);
    float w2 = bw * bw / 12.0f, h2 = bh * bh / 12.0f;
    float a2 = w2*cs*cs + h2*sn*sn;
    float b2 = w2*sn*sn + h2*cs*cs;
    float c2 = (w2 - h2) * cs * sn;
    float d2 = fmaxf(a2*b2 - c2*c2, 0.f);
    float d2s = d2 * __frsqrt_rn(fmaxf(d2, 1e-30f));
    g_bx[t] = bx; g_by[t] = by;
    g_a2[t] = a2; g_b2[t] = b2; g_c2[t] = c2;
    g_d2s[t] = d2s;
    g_ld2[t] = __logf(fmaxf(d2s, 1e-35f));
    g_obj[t] = r5;
    float so = __fdividef(1.f, 1.f + __expf(-r5));
    float S = 0.f;
    #pragma unroll
    for (int c = 0; c < NC; c++) {
        float x = p0[(6 + c) * hw];
        float sc = __fdividef(1.f, 1.f + __expf(-x));
        float q = sc * so;
        float p = q * __frsqrt_rn(fmaxf(q, 1e-30f));
        p = fminf(fmaxf(p, 1e-7f), 1.f - 1e-7f);
        float lg = __logf(1.f - p);
        float lp = __logf(p);
        S -= lg;
        g_lc[c * BA + t] = lg - lp;
    }
    g_S[t] = S;
}

// ---------------- K2: dense ious + cost (anchors 2i,2i+1 per thread) ----------------
__global__ void k_cost() {
    int b = blockIdx.x / 84;
    int tile = blockIdx.x - b * 84;
    int tid = threadIdx.x;
    int a0 = tile * 256 + 2 * tid;
    int t0 = b * NA + a0;
    __shared__ float s_cx[NG], s_cy[NG], s_hw[NG], s_hh[NG];
    __shared__ float s_a1[NG], s_b1[NG], s_c1[NG], s_ld1[NG];
    __shared__ int   s_cls[NG], s_val[NG];
    if (tid < NG) {
        int gi = b * NG + tid;
        int v = g_gvalid[gi];
        s_val[tid] = v;
        s_cx[tid] = v ? g_gcx[gi] : 3.0e9f;
        s_cy[tid] = v ? g_gcy[gi] : 3.0e9f;
        s_hw[tid] = g_ghw[gi]; s_hh[tid] = g_ghh[gi];
        s_a1[tid] = g_ga1[gi]; s_b1[tid] = g_gb1[gi];
        s_c1[tid] = g_gc1[gi]; s_ld1[tid] = g_gld1[gi];
        s_cls[tid] = g_gcls[gi];
    }
    __syncthreads();
    float st; int lvlbase, shx, mskx;
    if (a0 < L0N)      { st = 8.f;  lvlbase = 0;    shx = 7; mskx = 127; }
    else if (a0 < L1N) { st = 16.f; lvlbase = L0N;  shx = 6; mskx = 63; }
    else               { st = 32.f; lvlbase = L1N;  shx = 5; mskx = 31; }
    int i0 = a0 - lvlbase;
    float xc0 = ((float)(i0 & mskx) + 0.5f) * st;
    float yc0 = ((float)(i0 >> shx) + 0.5f) * st;
    float xc1 = xc0 + st;
    float rad = 2.5f * st;

    float2 bx01 = *(const float2*)&g_bx[t0];
    float2 by01 = *(const float2*)&g_by[t0];
    float2 A01  = *(const float2*)&g_a2[t0];
    float2 B01  = *(const float2*)&g_b2[t0];
    float2 C01  = *(const float2*)&g_c2[t0];
    float2 S01  = *(const float2*)&g_S[t0];
    float2 ld01 = *(const float2*)&g_ld2[t0];
    float lb0 = ld01.x + LOG4F, lb1 = ld01.y + LOG4F;

    unsigned long long both0 = 0ULL, both1 = 0ULL;
    bool c0 = false, c1 = false;
    #pragma unroll 4
    for (int g = 0; g < NG; g++) {
        float cx = s_cx[g], cy = s_cy[g], hwv = s_hw[g], hh = s_hh[g];
        float dx0 = fabsf(xc0 - cx), dy0 = fabsf(yc0 - cy);
        float dx1 = fabsf(xc1 - cx);
        bool ib0 = (dx0 < hwv) & (dy0 < hh);
        bool ic0 = (dx0 < rad) & (dy0 < rad);
        bool ib1 = (dx1 < hwv) & (dy0 < hh);
        bool ic1 = (dx1 < rad) & (dy0 < rad);
        c0 |= ib0 | ic0; c1 |= ib1 | ic1;
        if (ib0 & ic0) both0 |= (1ULL << g);
        if (ib1 & ic1) both1 |= (1ULL << g);
    }
    float pc0 = c0 ? 0.f : 1e6f;
    float pc1 = c1 ? 0.f : 1e6f;
    size_t rowbase = (size_t)b * NG * NA + a0;

    for (int g = 0; g < NG; g++) {
        float4* dst = (float4*)(g_ic + rowbase + (size_t)g * NA);
        if (!s_val[g]) {
            *dst = make_float4(0.f, 2e9f, 0.f, 2e9f);
            continue;
        }
        float ga = s_a1[g], gb = s_b1[g], gc = s_c1[g];
        float cx = s_cx[g], cy = s_cy[g];
        float lg1 = s_ld1[g];
        float2 lc = *(const float2*)&g_lc[s_cls[g] * BA + t0];
        float4 o;
        {
            float Af = ga + A01.x, Bf = gb + B01.x, Cf = gc + C01.x;
            float dx = cx - bx01.x, dy = cy - by01.x;
            float den = Af * Bf - Cf * Cf + 1e-8f;
            float rden = __fdividef(1.f, den);
            float t1 = 0.25f * (Af*dy*dy + Bf*dx*dx) * rden;
            float t2 = -0.5f * Cf * dx * dy * rden;
            float t3 = 0.5f * (__logf(den) - (lg1 + lb0));
            float bd = fminf(fmaxf(t1 + t2 + t3, 1e-8f), 100.f);
            float q = fminf(fmaxf(1.f - __expf(-bd), 1e-20f), 1.f);
            float iou = 1.f - q * __frsqrt_rn(q);
            float pb = ((both0 >> g) & 1ULL) ? 0.f : 1e5f;
            o.x = iou;
            o.y = fmaf(-3.f, __logf(iou + 1e-8f), S01.x + lc.x + pb + pc0);
        }
        {
            float Af = ga + A01.y, Bf = gb + B01.y, Cf = gc + C01.y;
            float dx = cx - bx01.y, dy = cy - by01.y;
            float den = Af * Bf - Cf * Cf + 1e-8f;
            float rden = __fdividef(1.f, den);
            float t1 = 0.25f * (Af*dy*dy + Bf*dx*dx) * rden;
            float t2 = -0.5f * Cf * dx * dy * rden;
            float t3 = 0.5f * (__logf(den) - (lg1 + lb1));
            float bd = fminf(fmaxf(t1 + t2 + t3, 1e-8f), 100.f);
            float q = fminf(fmaxf(1.f - __expf(-bd), 1e-20f), 1.f);
            float iou = 1.f - q * __frsqrt_rn(q);
            float pb = ((both1 >> g) & 1ULL) ? 0.f : 1e5f;
            o.z = iou;
            o.w = fmaf(-3.f, __logf(iou + 1e-8f), S01.y + lc.y + pb + pc1);
        }
        *dst = o;
    }
}

// ---------------- selection helpers (warp-distributed lists, lanes 0..9) ----------------
__device__ __forceinline__ bool pless(float c1, int i1, float c2, int i2) {
    return (c1 < c2) || (c1 == c2 && i1 < i2);
}
__device__ __forceinline__ void wins_top(float& tv, int lane, float c) {
    unsigned bm = __ballot_sync(FULLM, (lane < 10) && (c > tv)) & 0x3FFu;
    if (bm) {
        int p = __ffs(bm) - 1;
        float up = __shfl_up_sync(FULLM, tv, 1);
        if (lane < 10 && lane >= p) tv = (lane == p) ? c : up;
    }
}
__device__ __forceinline__ void wins_bot(float& bcv, int& biv, int lane, float c, int i) {
    unsigned bm = __ballot_sync(FULLM, (lane < 10) && pless(c, i, bcv, biv)) & 0x3FFu;
    if (bm) {
        int p = __ffs(bm) - 1;
        float uc = __shfl_up_sync(FULLM, bcv, 1);
        int   ui = __shfl_up_sync(FULLM, biv, 1);
        if (lane < 10 && lane >= p) { bcv = (lane == p) ? c : uc; biv = (lane == p) ? i : ui; }
    }
}

// ---------------- K3a: per-(b,g,segment) partials ----------------
// Common case: 1 LDG.128 + ~10 ALU + 1 ballot per 2 anchors. Replicated conservative-stale
// thresholds in every lane's registers; insert bursts only on (warp-uniform) ballot hits.
__global__ void k_sel1() {
    int bg = blockIdx.x >> 2;
    int part = blockIdx.x & 3;
    if (!g_gvalid[bg]) return;
    int w = threadIdx.x >> 5, lane = threadIdx.x & 31;
    int seg = part * 4 + w;                 // 0..15
    const float4* __restrict__ row4 = (const float4*)(g_ic + (size_t)bg * NA);
    int base = seg * 672;                   // 672 f4 = 1344 anchors per segment; 21 iters

    float tv = 0.f; float bcv = 3.0e38f; int biv = 0x7fffffff;   // distributed lists
    float thr_t = 0.f; float thr_c = 3.0e38f; int thr_i = 0x7fffffff;  // replicated thresholds

    float4 f0 = row4[base + lane];
    float4 f1 = row4[base + 32 + lane];
    #pragma unroll 1
    for (int s = 0; s < 21; s++) {
        float4 f2;
        if (s < 19) f2 = row4[base + (s + 2) * 32 + lane];
        int fi = base + s * 32 + lane;
        float e0 = (f0.y < 1e6f) ? f0.x : 0.f;   // cand <=> cost < 1e6 (penalty separation)
        float e1 = (f0.w < 1e6f) ? f0.z : 0.f;
        float em = fmaxf(e0, e1);
        float cm = fminf(f0.y, f0.w);
        bool need = (em > thr_t) | (cm <= thr_c);    // conservative (ties included)
        unsigned nb = __ballot_sync(FULLM, need);
        if (nb) {
            unsigned mt = __ballot_sync(FULLM, em > thr_t);
            unsigned mc = __ballot_sync(FULLM, (cm < thr_c) || (cm == thr_c && 2*fi <= thr_i));
            while (mt) {
                int src = __ffs(mt) - 1; mt &= mt - 1;
                wins_top(tv, lane, __shfl_sync(FULLM, e0, src));
                wins_top(tv, lane, __shfl_sync(FULLM, e1, src));
            }
            thr_t = __shfl_sync(FULLM, tv, 9);
            while (mc) {
                int src = __ffs(mc) - 1; mc &= mc - 1;
                int ab = 2 * (base + s * 32 + src);
                wins_bot(bcv, biv, lane, __shfl_sync(FULLM, f0.y, src), ab);
                wins_bot(bcv, biv, lane, __shfl_sync(FULLM, f0.w, src), ab + 1);
            }
            thr_c = __shfl_sync(FULLM, bcv, 9);
            thr_i = __shfl_sync(FULLM, biv, 9);
        }
        f0 = f1; f1 = f2;
    }
    if (lane < 10) {
        int o = (bg * NSEG + seg) * 10 + lane;
        g_pt[o] = tv; g_pc[o] = bcv; g_pi[o] = biv;
    }
}

// ---------------- K3b: merge 16 segment partials per (b,g) ----------------
__global__ void k_sel2() {
    int bg = blockIdx.x;
    int lane = threadIdx.x;
    if (!g_gvalid[bg]) {
        if (lane == 0) { g_dynk[bg] = 0; g_thrC[bg] = -3.0e38f; g_thrI[bg] = -1; }
        return;
    }
    const float* __restrict__ pt = g_pt + (size_t)bg * NSEG * 10;
    const float* __restrict__ pcr = g_pc + (size_t)bg * NSEG * 10;
    const int*   __restrict__ pir = g_pi + (size_t)bg * NSEG * 10;

    float tv = 0.f, bcv = 3.0e38f; int biv = 0x7fffffff;
    float thr_t = 0.f, thr_c = 3.0e38f; int thr_i = 0x7fffffff;
    #pragma unroll
    for (int i = 0; i < 5; i++) {           // 160 entries in 5 batches of 32
        int e = i * 32 + lane;
        bool ok = e < NSEG * 10;
        float a = ok ? pt[e]  : 0.f;
        float c = ok ? pcr[e] : 3.0e38f;
        int  ix = ok ? pir[e] : 0x7fffffff;
        unsigned mt = __ballot_sync(FULLM, a > thr_t);
        unsigned mc = __ballot_sync(FULLM, (c < thr_c) || (c == thr_c && ix < thr_i));
        while (mt) {
            int src = __ffs(mt) - 1; mt &= mt - 1;
            wins_top(tv, lane, __shfl_sync(FULLM, a, src));
        }
        thr_t = __shfl_sync(FULLM, tv, 9);
        while (mc) {
            int src = __ffs(mc) - 1; mc &= mc - 1;
            float cs = __shfl_sync(FULLM, c, src);
            int  ii = __shfl_sync(FULLM, ix, src);
            wins_bot(bcv, biv, lane, cs, ii);
        }
        thr_c = __shfl_sync(FULLM, bcv, 9);
        thr_i = __shfl_sync(FULLM, biv, 9);
    }
    float x = (lane < 10) ? tv : 0.f;
    #pragma unroll
    for (int o = 16; o > 0; o >>= 1) x += __shfl_xor_sync(FULLM, x, o);
    int k = (int)x;
    if (k < 1) k = 1;
    if (k > 10) k = 10;
    float thrC = __shfl_sync(FULLM, bcv, k - 1);
    int   thrI = __shfl_sync(FULLM, biv, k - 1);
    if (lane == 0) { g_dynk[bg] = k; g_thrC[bg] = thrC; g_thrI[bg] = thrI; }
}

// ---------------- K5 tail helper: per-anchor fg losses ----------------
__device__ __forceinline__ void tail_loss(
    int b, int a, int t, int mg, float pi,
    const float* __restrict__ o8, const float* __restrict__ o16, const float* __restrict__ o32,
    const float* s_cx, const float* s_cy, const float* s_a1, const float* s_b1,
    const float* s_c1, const float* s_d1s, const int* s_cls,
    float& liou, float& lcls)
{
    float bx = g_bx[t], by = g_by[t];
    float a2 = g_a2[t], b2 = g_b2[t], c2 = g_c2[t], d2s = g_d2s[t];
    float Af = a2 + s_a1[mg], Bf = b2 + s_b1[mg], Cf = c2 + s_c1[mg];
    float dx = bx - s_cx[mg], dy = by - s_cy[mg];
    float den = Af * Bf - Cf * Cf + 1e-8f;
    float rden = __fdividef(1.f, den);
    float t1 = 0.25f * (Af*dy*dy + Bf*dx*dx) * rden;
    float t2 = -0.5f * Cf * dx * dy * rden;
    float t3 = 0.5f * __logf(__fdividef(den, 4.f * s_d1s[mg] * d2s + 1e-8f));
    float bd = fminf(fmaxf(t1 + t2 + t3, 1e-8f), 100.f);
    float q = fminf(fmaxf(1.f - __expf(-bd), 1e-20f), 1.f);
    float ioum = 1.f - q * __frsqrt_rn(q);
    liou += 1.f - ioum;
    const float* src; int hw, i;
    if (a < L0N)      { src = o8;  hw = 16384; i = a; }
    else if (a < L1N) { src = o16; hw = 4096;  i = a - L0N; }
    else              { src = o32; hw = 1024;  i = a - L1N; }
    const float* pc = src + ((size_t)b * 21 + 6) * hw + i;
    int mcls = s_cls[mg];
    #pragma unroll
    for (int c = 0; c < NC; c++) {
        float x = pc[(size_t)c * hw];
        float tg = (c == mcls) ? pi : 0.f;
        lcls += fmaxf(x, 0.f) - x * tg + __logf(1.f + __expf(-fabsf(x)));
    }
}

// ---------------- K5: match resolution + loss (2 anchors / thread) ----------------
__global__ void k_loss(const float* __restrict__ o8,
                       const float* __restrict__ o16,
                       const float* __restrict__ o32) {
    int b = blockIdx.x / 84;
    int tile = blockIdx.x - b * 84;
    int a0 = tile * 256 + 2 * threadIdx.x;
    int t0 = b * NA + a0;
    __shared__ float s_thrC[NG], s_cx[NG], s_cy[NG], s_a1[NG], s_b1[NG], s_c1[NG], s_d1s[NG];
    __shared__ int   s_thrI[NG], s_k[NG], s_cls[NG];
    if (threadIdx.x < NG) {
        int gi = b * NG + threadIdx.x;
        s_thrC[threadIdx.x] = g_thrC[gi]; s_thrI[threadIdx.x] = g_thrI[gi]; s_k[threadIdx.x] = g_dynk[gi];
        s_cx[threadIdx.x] = g_gcx[gi]; s_cy[threadIdx.x] = g_gcy[gi];
        s_a1[threadIdx.x] = g_ga1[gi]; s_b1[threadIdx.x] = g_gb1[gi]; s_c1[threadIdx.x] = g_gc1[gi];
        s_d1s[threadIdx.x] = g_gd1s[gi]; s_cls[threadIdx.x] = g_gcls[gi];
    }
    __syncthreads();
    const float4* __restrict__ col4 = (const float4*)(g_ic + (size_t)b * NG * NA + a0);
    int cnt0 = 0, cnt1 = 0, mg0 = 0, mg1 = 0, mn0 = 0, mn1 = 0;
    bool f0 = false, f1 = false;
    float minc0 = 3.4e38f, minc1 = 3.4e38f, mi0 = 0.f, mi1 = 0.f, ps0 = 0.f, ps1 = 0.f;
    #pragma unroll 4
    for (int g = 0; g < NG; g++) {
        float4 ic = col4[(size_t)g * (NA/2)];
        bool kk = s_k[g] > 0;
        bool m0 = kk && ((ic.y < s_thrC[g]) || (ic.y == s_thrC[g] && a0 <= s_thrI[g]));
        bool m1 = kk && ((ic.w < s_thrC[g]) || (ic.w == s_thrC[g] && a0 + 1 <= s_thrI[g]));
        if (m0) { cnt0++; if (!f0) { mg0 = g; f0 = true; } ps0 += ic.x; }
        if (m1) { cnt1++; if (!f1) { mg1 = g; f1 = true; } ps1 += ic.z; }
        if (ic.y < minc0) { minc0 = ic.y; mn0 = g; mi0 = ic.x; }
        if (ic.w < minc1) { minc1 = ic.w; mn1 = g; mi1 = ic.z; }
    }
    float pi0 = ps0, pi1 = ps1;
    if (cnt0 > 1) { mg0 = mn0; pi0 = mi0; }
    if (cnt1 > 1) { mg1 = mn1; pi1 = mi1; }
    bool fg0 = cnt0 > 0, fg1 = cnt1 > 0;
    float2 ob = *(const float2*)&g_obj[t0];
    float fo = (fg0 ? 1.f : 0.f) + (fg1 ? 1.f : 0.f);
    float lobj = fmaxf(ob.x, 0.f) - ob.x * (fg0 ? 1.f : 0.f) + __logf(1.f + __expf(-fabsf(ob.x)))
               + fmaxf(ob.y, 0.f) - ob.y * (fg1 ? 1.f : 0.f) + __logf(1.f + __expf(-fabsf(ob.y)));
    float liou = 0.f, lcls = 0.f;
    if (fg0) tail_loss(b, a0,     t0,     mg0, pi0, o8, o16, o32, s_cx, s_cy, s_a1, s_b1, s_c1, s_d1s, s_cls, liou, lcls);
    if (fg1) tail_loss(b, a0 + 1, t0 + 1, mg1, pi1, o8, o16, o32, s_cx, s_cy, s_a1, s_b1, s_c1, s_d1s, s_cls, liou, lcls);

    #pragma unroll
    for (int o = 16; o > 0; o >>= 1) {
        liou += __shfl_down_sync(FULLM, liou, o);
        lobj += __shfl_down_sync(FULLM, lobj, o);
        lcls += __shfl_down_sync(FULLM, lcls, o);
        fo   += __shfl_down_sync(FULLM, fo, o);
    }
    __shared__ float rs[4][4];
    int w = threadIdx.x >> 5, lane = threadIdx.x & 31;
    if (lane == 0) { rs[0][w] = liou; rs[1][w] = lobj; rs[2][w] = lcls; rs[3][w] = fo; }
    __syncthreads();
    if (threadIdx.x == 0) {
        atomicAdd(&g_acc[0], rs[0][0] + rs[0][1] + rs[0][2] + rs[0][3]);
        atomicAdd(&g_acc[1], rs[1][0] + rs[1][1] + rs[1][2] + rs[1][3]);
        atomicAdd(&g_acc[2], rs[2][0] + rs[2][1] + rs[2][2] + rs[2][3]);
        atomicAdd(&g_acc[3], rs[3][0] + rs[3][1] + rs[3][2] + rs[3][3]);
    }
}

// ---------------- K6: finalize ----------------
__global__ void k_final(float* __restrict__ out, int n) {
    if (threadIdx.x == 0) {
        float nfg = g_acc[3];
        float nf = fmaxf(nfg, 1.f);
        float liou = g_acc[0] / nf;
        float lobj = g_acc[1] / nf;
        float lcls = g_acc[2] / nf;
        float li5 = 5.f * liou;
        float loss = li5 + lobj + lcls;
        if (n > 0) out[0] = loss;
        if (n > 1) out[1] = li5;
        if (n > 2) out[2] = lobj;
        if (n > 3) out[3] = lcls;
        if (n > 4) out[4] = 0.f;
        if (n > 5) out[5] = nfg / fmaxf(g_acc[4], 1.f);
        for (int i = 6; i < n; i++) out[i] = 0.f;
    }
}

// ---------------- launch ----------------
extern "C" void kernel_launch(void* const* d_in, const int* in_sizes, int n_in,
                              void* d_out, int out_size) {
    const float* o8     = (const float*)d_in[0];
    const float* o16    = (const float*)d_in[1];
    const float* o32    = (const float*)d_in[2];
    const float* labels = (const float*)d_in[3];
    float* out = (float*)d_out;

    k_gt<<<1, 512>>>(labels);
    k_decode<<<BA / 128, 128>>>(o8, o16, o32);
    k_cost<<<NB * 84, 128>>>();
    k_sel1<<<NBG * 4, 128>>>();
    k_sel2<<<NBG, 32>>>();
    k_loss<<<NB * 84, 128>>>(o8, o16, o32);
    k_final<<<1, 32>>>(out, out_size);
}